// round 1
// baseline (speedup 1.0000x reference)
#include <cuda_runtime.h>

// Problem constants
#define BB 8
#define HH 64
#define WW 64
#define CC 128
#define FF 128
#define KKT 9
#define OO 18
#define TILE 32
#define VST 36   // sval row stride in floats (16B-aligned, decent bank spread)

// Scratch (device globals; no allocation allowed)
__device__ float g_offsets[BB * HH * WW * OO];        // [pix][18]
__device__ float g_kt[KKT * FF * CC];                 // [k][f][c]

// ---------------------------------------------------------------------------
// packed fp32x2 FMA (Blackwell): d = a*b + d, per-half rn
// ---------------------------------------------------------------------------
__device__ __forceinline__ void ffma2(float2& d, float2 a, float2 b) {
    unsigned long long ud = *reinterpret_cast<unsigned long long*>(&d);
    unsigned long long ua = *reinterpret_cast<unsigned long long*>(&a);
    unsigned long long ub = *reinterpret_cast<unsigned long long*>(&b);
    asm("fma.rn.f32x2 %0, %1, %2, %0;" : "+l"(ud) : "l"(ua), "l"(ub));
    d = *reinterpret_cast<float2*>(&ud);
}

// ---------------------------------------------------------------------------
// Kernel 0: transpose main weights [k, c, f] -> [k, f, c]
// ---------------------------------------------------------------------------
__global__ void kt_transpose(const float* __restrict__ kern) {
    int idx = blockIdx.x * 256 + threadIdx.x;
    if (idx < KKT * FF * CC) {
        int c = idx & (CC - 1);
        int rest = idx >> 7;           // idx / CC
        int f = rest & (FF - 1);
        int k = rest >> 7;             // rest / FF
        g_kt[idx] = kern[(k * CC + c) * FF + f];
    }
}

// ---------------------------------------------------------------------------
// Kernel 1: offset-predicting 3x3 conv (SAME), out [pix][18]
// One 128-thread block per pixel; thread = input channel.
// ---------------------------------------------------------------------------
__global__ __launch_bounds__(128) void offsets_conv(
    const float* __restrict__ x,
    const float* __restrict__ ow,
    const float* __restrict__ ob)
{
    int pix = blockIdx.x;
    int b = pix >> 12;
    int rem = pix & 4095;
    int y = rem >> 6;
    int xw = rem & 63;
    int c = threadIdx.x;

    float acc[OO];
#pragma unroll
    for (int o = 0; o < OO; o++) acc[o] = 0.f;

#pragma unroll
    for (int kh = 0; kh < 3; kh++) {
        int iy = y + kh - 1;
        if ((unsigned)iy >= HH) continue;
#pragma unroll
        for (int kw = 0; kw < 3; kw++) {
            int ix = xw + kw - 1;
            if ((unsigned)ix >= WW) continue;
            float xv = x[(((b * HH + iy) * WW) + ix) * CC + c];
            const float* wrow = ow + ((kh * 3 + kw) * CC + c) * OO;
#pragma unroll
            for (int o = 0; o < OO; o++) acc[o] = fmaf(xv, wrow[o], acc[o]);
        }
    }

    // warp reduce each of the 18 sums
#pragma unroll
    for (int o = 0; o < OO; o++) {
#pragma unroll
        for (int s = 16; s; s >>= 1)
            acc[o] += __shfl_down_sync(0xffffffffu, acc[o], s);
    }

    __shared__ float red[4][OO];
    int lane = c & 31, wid = c >> 5;
    if (lane == 0) {
#pragma unroll
        for (int o = 0; o < OO; o++) red[wid][o] = acc[o];
    }
    __syncthreads();
    if (c < OO) {
        g_offsets[pix * OO + c] =
            red[0][c] + red[1][c] + red[2][c] + red[3][c] + ob[c];
    }
}

// ---------------------------------------------------------------------------
// Kernel 2: fused bilinear sampling + tap-GEMM + bias
// Block = 128 threads, TILE=32 consecutive pixels (one row segment).
// Phase A (thread = channel): bilinear sample tap k for all 32 pixels -> smem.
// Phase B (thread = output f): f32x2-packed dot over 128 channels.
// ---------------------------------------------------------------------------
__global__ __launch_bounds__(128) void deform_main(
    const float* __restrict__ x,
    const float* __restrict__ bias,
    float* __restrict__ out)
{
    __shared__ float  sval[CC * VST];
    __shared__ int2   spos[TILE * KKT];
    __shared__ float4 swt[TILE * KKT];

    int tid = threadIdx.x;
    int pbase = blockIdx.x * TILE;
    int b = pbase >> 12;
    int rem = pbase & 4095;
    int y = rem >> 6;
    int xw0 = rem & 63;

    // setup: per (pixel, tap) sampling position + bilinear weights
    for (int i = tid; i < TILE * KKT; i += 128) {
        int t = i / KKT;
        int k = i - t * KKT;
        float dy = g_offsets[(pbase + t) * OO + 2 * k];
        float dx = g_offsets[(pbase + t) * OO + 2 * k + 1];
        float py = (float)y + (float)(k / 3 - 1) + dy;
        float px = (float)(xw0 + t) + (float)(k % 3 - 1) + dx;
        float fy = floorf(py), fx = floorf(px);
        float wy = py - fy, wx = px - fx;
        spos[i] = make_int2((int)fy, (int)fx);
        swt[i] = make_float4((1.f - wy) * (1.f - wx), (1.f - wy) * wx,
                             wy * (1.f - wx), wy * wx);
    }
    __syncthreads();

    float bv = bias[tid];
    float2 acc[TILE / 2];
#pragma unroll
    for (int j = 0; j < TILE / 2; j++) acc[j] = make_float2(0.f, 0.f);

    const float* xb = x + (size_t)b * HH * WW * CC;

    for (int k = 0; k < KKT; k++) {
        // Phase A: sampling (thread = channel tid)
#pragma unroll
        for (int t = 0; t < TILE; t++) {
            int i = t * KKT + k;
            int2 p = spos[i];
            float4 w = swt[i];
            int y0 = p.x, x0 = p.y;
            bool vy0 = (unsigned)y0 < HH;
            bool vy1 = (unsigned)(y0 + 1) < HH;
            bool vx0 = (unsigned)x0 < WW;
            bool vx1 = (unsigned)(x0 + 1) < WW;
            const float* base = xb + ((y0 * WW + x0) * CC) + tid;
            float v00 = (vy0 && vx0) ? base[0] : 0.f;
            float v01 = (vy0 && vx1) ? base[CC] : 0.f;
            float v10 = (vy1 && vx0) ? base[WW * CC] : 0.f;
            float v11 = (vy1 && vx1) ? base[WW * CC + CC] : 0.f;
            sval[tid * VST + t] = w.x * v00 + w.y * v01 + w.z * v10 + w.w * v11;
        }
        __syncthreads();

        // Phase B: accumulate (thread = output feature tid)
        const float4* kt4 = (const float4*)(g_kt + (k * FF + tid) * CC);
#pragma unroll
        for (int c4 = 0; c4 < CC / 4; c4++) {
            float4 w4 = kt4[c4];
#pragma unroll
            for (int j = 0; j < 4; j++) {
                int c = c4 * 4 + j;
                float wv = (j == 0) ? w4.x : (j == 1) ? w4.y : (j == 2) ? w4.z : w4.w;
                float2 wp = make_float2(wv, wv);
                const float4* vr = (const float4*)&sval[c * VST];
#pragma unroll
                for (int t4 = 0; t4 < TILE / 4; t4++) {
                    float4 v = vr[t4];
                    ffma2(acc[t4 * 2],     make_float2(v.x, v.y), wp);
                    ffma2(acc[t4 * 2 + 1], make_float2(v.z, v.w), wp);
                }
            }
        }
        __syncthreads();
    }

    // epilogue: bias + store
#pragma unroll
    for (int j = 0; j < TILE / 2; j++) {
        out[(size_t)(pbase + 2 * j) * FF + tid] = acc[j].x + bv;
        out[(size_t)(pbase + 2 * j + 1) * FF + tid] = acc[j].y + bv;
    }
}

// ---------------------------------------------------------------------------
extern "C" void kernel_launch(void* const* d_in, const int* in_sizes, int n_in,
                              void* d_out, int out_size)
{
    const float* x        = (const float*)d_in[0];
    const float* kern     = (const float*)d_in[1];
    const float* bias     = (const float*)d_in[2];
    const float* offset_w = (const float*)d_in[3];
    const float* offset_b = (const float*)d_in[4];
    float* out = (float*)d_out;

    kt_transpose<<<(KKT * FF * CC + 255) / 256, 256>>>(kern);
    offsets_conv<<<BB * HH * WW, 128>>>(x, offset_w, offset_b);
    deform_main<<<(BB * HH * WW) / TILE, 128>>>(x, bias, out);
}

// round 2
// speedup vs baseline: 2.4217x; 2.4217x over previous
#include <cuda_runtime.h>

// Problem constants
#define BB 8
#define HH 64
#define WW 64
#define CC 128
#define FF 128
#define KKT 9
#define OO 18
#define TILE 32
#define VST 36   // sval row stride in floats

// Scratch (device globals; no allocation allowed)
__device__ float g_offsets[BB * HH * WW * OO];        // [pix][18]
__device__ float g_kt[KKT * FF * CC];                 // [k][f][c]
__device__ float g_owt[KKT * OO * CC];                // [k][o][c]

// ---------------------------------------------------------------------------
// packed fp32x2 FMA (Blackwell): d = a*b + d
// ---------------------------------------------------------------------------
__device__ __forceinline__ void ffma2(float2& d, float2 a, float2 b) {
    unsigned long long ud = *reinterpret_cast<unsigned long long*>(&d);
    unsigned long long ua = *reinterpret_cast<unsigned long long*>(&a);
    unsigned long long ub = *reinterpret_cast<unsigned long long*>(&b);
    asm("fma.rn.f32x2 %0, %1, %2, %0;" : "+l"(ud) : "l"(ua), "l"(ub));
    d = *reinterpret_cast<float2*>(&ud);
}

// launch-index alignment helper so ncu -s 5 lands on deform_main
__global__ void noop_align() {}

// ---------------------------------------------------------------------------
// Kernel 0: transpose main weights [k,c,f]->[k,f,c] and offset weights
// [k,c,o]->[k,o,c]
// ---------------------------------------------------------------------------
#define KT_N (KKT * FF * CC)
#define OWT_N (KKT * OO * CC)
__global__ void transpose_weights(const float* __restrict__ kern,
                                  const float* __restrict__ ow) {
    int idx = blockIdx.x * 256 + threadIdx.x;
    if (idx < KT_N) {
        int c = idx & (CC - 1);
        int rest = idx >> 7;
        int f = rest & (FF - 1);
        int k = rest >> 7;
        g_kt[idx] = kern[(k * CC + c) * FF + f];
    }
    int idx2 = idx - KT_N;
    if (idx2 >= 0 && idx2 < OWT_N) {
        int c = idx2 & (CC - 1);
        int rest = idx2 >> 7;
        int o = rest % OO;
        int k = rest / OO;
        g_owt[idx2] = ow[(k * CC + c) * OO + o];
    }
}

// ---------------------------------------------------------------------------
// Kernel 1: offset-predicting 3x3 conv (SAME), out [pix][18]
// 1 warp handles 2 adjacent pixels; lane = 4 channels (float4, coalesced).
// Weights read from transposed layout g_owt[k][o][c] -> coalesced float4.
// ---------------------------------------------------------------------------
__global__ __launch_bounds__(128) void offsets_conv(
    const float* __restrict__ x,
    const float* __restrict__ ob)
{
    int warp = threadIdx.x >> 5;
    int lane = threadIdx.x & 31;
    int pixA = blockIdx.x * 8 + warp * 2;   // pixA even-in-row; pixB = pixA+1
    int b = pixA >> 12;
    int rem = pixA & 4095;
    int y = rem >> 6;
    int xw = rem & 63;                       // <= 62, so xw+1 in same row

    float2 accA[OO], accB[OO];
#pragma unroll
    for (int o = 0; o < OO; o++) { accA[o] = make_float2(0.f, 0.f); accB[o] = make_float2(0.f, 0.f); }

    const float* xb = x + (size_t)b * HH * WW * CC;

#pragma unroll
    for (int k = 0; k < KKT; k++) {
        int iy = y + k / 3 - 1;
        int ixA = xw + k % 3 - 1;
        float4 xA = make_float4(0.f, 0.f, 0.f, 0.f);
        float4 xB = make_float4(0.f, 0.f, 0.f, 0.f);
        if ((unsigned)iy < HH) {
            const float* rowp = xb + ((size_t)iy * WW) * CC + 4 * lane;
            if ((unsigned)ixA < WW) xA = *(const float4*)(rowp + ixA * CC);
            if ((unsigned)(ixA + 1) < WW) xB = *(const float4*)(rowp + (ixA + 1) * CC);
        }
        const float4* wv = (const float4*)(g_owt + k * OO * CC) + lane;
#pragma unroll
        for (int o = 0; o < OO; o++) {
            float4 w4 = wv[o * (CC / 4)];
            ffma2(accA[o], make_float2(xA.x, xA.y), make_float2(w4.x, w4.y));
            ffma2(accA[o], make_float2(xA.z, xA.w), make_float2(w4.z, w4.w));
            ffma2(accB[o], make_float2(xB.x, xB.y), make_float2(w4.x, w4.y));
            ffma2(accB[o], make_float2(xB.z, xB.w), make_float2(w4.z, w4.w));
        }
    }

    // horizontal + warp reduce, then lane 0 stores
#pragma unroll
    for (int o = 0; o < OO; o++) {
        float sA = accA[o].x + accA[o].y;
        float sB = accB[o].x + accB[o].y;
#pragma unroll
        for (int s = 16; s; s >>= 1) {
            sA += __shfl_down_sync(0xffffffffu, sA, s);
            sB += __shfl_down_sync(0xffffffffu, sB, s);
        }
        if (lane == 0) {
            float bo = ob[o];
            g_offsets[(size_t)pixA * OO + o] = sA + bo;
            g_offsets[(size_t)(pixA + 1) * OO + o] = sB + bo;
        }
    }
}

// ---------------------------------------------------------------------------
// Kernel 2: fused bilinear sampling + tap-GEMM + bias (unchanged from R1)
// ---------------------------------------------------------------------------
__global__ __launch_bounds__(128) void deform_main(
    const float* __restrict__ x,
    const float* __restrict__ bias,
    float* __restrict__ out)
{
    __shared__ float  sval[CC * VST];
    __shared__ int2   spos[TILE * KKT];
    __shared__ float4 swt[TILE * KKT];

    int tid = threadIdx.x;
    int pbase = blockIdx.x * TILE;
    int b = pbase >> 12;
    int rem = pbase & 4095;
    int y = rem >> 6;
    int xw0 = rem & 63;

    for (int i = tid; i < TILE * KKT; i += 128) {
        int t = i / KKT;
        int k = i - t * KKT;
        float dy = g_offsets[(pbase + t) * OO + 2 * k];
        float dx = g_offsets[(pbase + t) * OO + 2 * k + 1];
        float py = (float)y + (float)(k / 3 - 1) + dy;
        float px = (float)(xw0 + t) + (float)(k % 3 - 1) + dx;
        float fy = floorf(py), fx = floorf(px);
        float wy = py - fy, wx = px - fx;
        spos[i] = make_int2((int)fy, (int)fx);
        swt[i] = make_float4((1.f - wy) * (1.f - wx), (1.f - wy) * wx,
                             wy * (1.f - wx), wy * wx);
    }
    __syncthreads();

    float bv = bias[tid];
    float2 acc[TILE / 2];
#pragma unroll
    for (int j = 0; j < TILE / 2; j++) acc[j] = make_float2(0.f, 0.f);

    const float* xb = x + (size_t)b * HH * WW * CC;

    for (int k = 0; k < KKT; k++) {
#pragma unroll
        for (int t = 0; t < TILE; t++) {
            int i = t * KKT + k;
            int2 p = spos[i];
            float4 w = swt[i];
            int y0 = p.x, x0 = p.y;
            bool vy0 = (unsigned)y0 < HH;
            bool vy1 = (unsigned)(y0 + 1) < HH;
            bool vx0 = (unsigned)x0 < WW;
            bool vx1 = (unsigned)(x0 + 1) < WW;
            const float* base = xb + ((y0 * WW + x0) * CC) + tid;
            float v00 = (vy0 && vx0) ? base[0] : 0.f;
            float v01 = (vy0 && vx1) ? base[CC] : 0.f;
            float v10 = (vy1 && vx0) ? base[WW * CC] : 0.f;
            float v11 = (vy1 && vx1) ? base[WW * CC + CC] : 0.f;
            sval[tid * VST + t] = w.x * v00 + w.y * v01 + w.z * v10 + w.w * v11;
        }
        __syncthreads();

        const float4* kt4 = (const float4*)(g_kt + (k * FF + tid) * CC);
#pragma unroll
        for (int c4 = 0; c4 < CC / 4; c4++) {
            float4 w4 = kt4[c4];
#pragma unroll
            for (int j = 0; j < 4; j++) {
                int c = c4 * 4 + j;
                float wv = (j == 0) ? w4.x : (j == 1) ? w4.y : (j == 2) ? w4.z : w4.w;
                float2 wp = make_float2(wv, wv);
                const float4* vr = (const float4*)&sval[c * VST];
#pragma unroll
                for (int t4 = 0; t4 < TILE / 4; t4++) {
                    float4 v = vr[t4];
                    ffma2(acc[t4 * 2],     make_float2(v.x, v.y), wp);
                    ffma2(acc[t4 * 2 + 1], make_float2(v.z, v.w), wp);
                }
            }
        }
        __syncthreads();
    }

#pragma unroll
    for (int j = 0; j < TILE / 2; j++) {
        out[(size_t)(pbase + 2 * j) * FF + tid] = acc[j].x + bv;
        out[(size_t)(pbase + 2 * j + 1) * FF + tid] = acc[j].y + bv;
    }
}

// ---------------------------------------------------------------------------
extern "C" void kernel_launch(void* const* d_in, const int* in_sizes, int n_in,
                              void* d_out, int out_size)
{
    const float* x        = (const float*)d_in[0];
    const float* kern     = (const float*)d_in[1];
    const float* bias     = (const float*)d_in[2];
    const float* offset_w = (const float*)d_in[3];
    const float* offset_b = (const float*)d_in[4];
    float* out = (float*)d_out;

    noop_align<<<1, 32>>>();
    transpose_weights<<<(KT_N + OWT_N + 255) / 256, 256>>>(kern, offset_w);
    offsets_conv<<<(BB * HH * WW) / 8, 128>>>(x, offset_b);
    deform_main<<<(BB * HH * WW) / TILE, 128>>>(x, bias, out);
}

// round 4
// speedup vs baseline: 4.0025x; 1.6528x over previous
#include <cuda_runtime.h>

// Problem constants
#define BB 8
#define HH 64
#define WW 64
#define CC 128
#define FF 128
#define KKT 9
#define OO 18
#define TILE 32
#define VST 36   // sval row stride in floats (16B-aligned LDS.128, bounded conflicts)

// Scratch (device globals; no allocation allowed)
__device__ float g_offsets[BB * HH * WW * OO];        // [pix][18]
__device__ float g_owt[KKT * OO * CC];                // [k][o][c]

// ---------------------------------------------------------------------------
// packed fp32x2 FMA (Blackwell): d = a*b + d
// ---------------------------------------------------------------------------
__device__ __forceinline__ void ffma2(float2& d, float2 a, float2 b) {
    unsigned long long ud = *reinterpret_cast<unsigned long long*>(&d);
    unsigned long long ua = *reinterpret_cast<unsigned long long*>(&a);
    unsigned long long ub = *reinterpret_cast<unsigned long long*>(&b);
    asm("fma.rn.f32x2 %0, %1, %2, %0;" : "+l"(ud) : "l"(ua), "l"(ub));
    d = *reinterpret_cast<float2*>(&ud);
}

// launch-index alignment helper so ncu -s 5 lands on deform_main
__global__ void noop_align() {}

// ---------------------------------------------------------------------------
// Kernel 0: transpose offset weights [k,c,o] -> [k,o,c]
// ---------------------------------------------------------------------------
#define OWT_N (KKT * OO * CC)
__global__ void transpose_weights(const float* __restrict__ ow) {
    int idx = blockIdx.x * 256 + threadIdx.x;
    if (idx < OWT_N) {
        int c = idx & (CC - 1);
        int rest = idx >> 7;
        int o = rest % OO;
        int k = rest / OO;
        g_owt[idx] = ow[(k * CC + c) * OO + o];
    }
}

// ---------------------------------------------------------------------------
// Kernel 1: offset-predicting 3x3 conv (SAME), out [pix][18]
// 1 warp handles 2 adjacent pixels; lane = 4 channels (float4, coalesced).
// ---------------------------------------------------------------------------
__global__ __launch_bounds__(128) void offsets_conv(
    const float* __restrict__ x,
    const float* __restrict__ ob)
{
    int warp = threadIdx.x >> 5;
    int lane = threadIdx.x & 31;
    int pixA = blockIdx.x * 8 + warp * 2;
    int b = pixA >> 12;
    int rem = pixA & 4095;
    int y = rem >> 6;
    int xw = rem & 63;

    float2 accA[OO], accB[OO];
#pragma unroll
    for (int o = 0; o < OO; o++) { accA[o] = make_float2(0.f, 0.f); accB[o] = make_float2(0.f, 0.f); }

    const float* xb = x + (size_t)b * HH * WW * CC;

#pragma unroll
    for (int k = 0; k < KKT; k++) {
        int iy = y + k / 3 - 1;
        int ixA = xw + k % 3 - 1;
        float4 xA = make_float4(0.f, 0.f, 0.f, 0.f);
        float4 xB = make_float4(0.f, 0.f, 0.f, 0.f);
        if ((unsigned)iy < HH) {
            const float* rowp = xb + ((size_t)iy * WW) * CC + 4 * lane;
            if ((unsigned)ixA < WW) xA = *(const float4*)(rowp + ixA * CC);
            if ((unsigned)(ixA + 1) < WW) xB = *(const float4*)(rowp + (ixA + 1) * CC);
        }
        const float4* wv = (const float4*)(g_owt + k * OO * CC) + lane;
#pragma unroll
        for (int o = 0; o < OO; o++) {
            float4 w4 = wv[o * (CC / 4)];
            ffma2(accA[o], make_float2(xA.x, xA.y), make_float2(w4.x, w4.y));
            ffma2(accA[o], make_float2(xA.z, xA.w), make_float2(w4.z, w4.w));
            ffma2(accB[o], make_float2(xB.x, xB.y), make_float2(w4.x, w4.y));
            ffma2(accB[o], make_float2(xB.z, xB.w), make_float2(w4.z, w4.w));
        }
    }

#pragma unroll
    for (int o = 0; o < OO; o++) {
        float sA = accA[o].x + accA[o].y;
        float sB = accB[o].x + accB[o].y;
#pragma unroll
        for (int s = 16; s; s >>= 1) {
            sA += __shfl_down_sync(0xffffffffu, sA, s);
            sB += __shfl_down_sync(0xffffffffu, sB, s);
        }
        if (lane == 0) {
            float bo = ob[o];
            g_offsets[(size_t)pixA * OO + o] = sA + bo;
            g_offsets[(size_t)(pixA + 1) * OO + o] = sB + bo;
        }
    }
}

// ---------------------------------------------------------------------------
// Kernel 2: fused bilinear sampling + register-tiled tap-GEMM + bias
// Block = 128 threads, TILE=32 pixels (one row segment).
// Phase A (thread = channel): bilinear sample tap k for 32 pixels -> smem.
// Phase B: thread = (pg, fg); computes 4 pixels x 8 features outer product.
//   Per channel: 1 LDS.128 (pixels) + 2 LDG.128 (weights, native [k][c][f]
//   layout, L1-resident) feeding 16 FFMA2.
// ---------------------------------------------------------------------------
__global__ __launch_bounds__(128) void deform_main(
    const float* __restrict__ x,
    const float* __restrict__ kern,
    const float* __restrict__ bias,
    float* __restrict__ out)
{
    __shared__ float  sval[CC * VST];
    __shared__ int2   spos[TILE * KKT];
    __shared__ float4 swt[TILE * KKT];

    int tid = threadIdx.x;
    int fg = tid >> 3;          // 0..15 : feature group (8 features)
    int pg = tid & 7;           // 0..7  : pixel group (4 pixels)

    int pbase = blockIdx.x * TILE;
    int b = pbase >> 12;
    int rem = pbase & 4095;
    int y = rem >> 6;
    int xw0 = rem & 63;

    // setup: per (pixel, tap) sampling position + bilinear weights
    for (int i = tid; i < TILE * KKT; i += 128) {
        int t = i / KKT;
        int k = i - t * KKT;
        float dy = g_offsets[(pbase + t) * OO + 2 * k];
        float dx = g_offsets[(pbase + t) * OO + 2 * k + 1];
        float py = (float)y + (float)(k / 3 - 1) + dy;
        float px = (float)(xw0 + t) + (float)(k % 3 - 1) + dx;
        float fy = floorf(py), fx = floorf(px);
        float wy = py - fy, wx = px - fx;
        spos[i] = make_int2((int)fy, (int)fx);
        swt[i] = make_float4((1.f - wy) * (1.f - wx), (1.f - wy) * wx,
                             wy * (1.f - wx), wy * wx);
    }
    __syncthreads();

    float2 acc[4][4];
#pragma unroll
    for (int p = 0; p < 4; p++)
#pragma unroll
        for (int j = 0; j < 4; j++) acc[p][j] = make_float2(0.f, 0.f);

    const float* xb = x + (size_t)b * HH * WW * CC;

    for (int k = 0; k < KKT; k++) {
        // ---- Phase A: bilinear sampling (thread = channel tid) ----
#pragma unroll
        for (int t = 0; t < TILE; t++) {
            int i = t * KKT + k;
            int2 p = spos[i];
            float4 w = swt[i];
            int y0 = p.x, x0 = p.y;
            bool vy0 = (unsigned)y0 < HH;
            bool vy1 = (unsigned)(y0 + 1) < HH;
            bool vx0 = (unsigned)x0 < WW;
            bool vx1 = (unsigned)(x0 + 1) < WW;
            const float* base = xb + ((y0 * WW + x0) * CC) + tid;
            float v00 = (vy0 && vx0) ? base[0] : 0.f;
            float v01 = (vy0 && vx1) ? base[CC] : 0.f;
            float v10 = (vy1 && vx0) ? base[WW * CC] : 0.f;
            float v11 = (vy1 && vx1) ? base[WW * CC + CC] : 0.f;
            sval[tid * VST + t] = w.x * v00 + w.y * v01 + w.z * v10 + w.w * v11;
        }
        __syncthreads();

        // ---- Phase B: 4px x 8f outer product over 128 channels ----
        const float* wk = kern + ((size_t)k * CC) * FF + fg * 8;
        const float* sv = sval + pg * 4;
#pragma unroll 4
        for (int c = 0; c < CC; c++) {
            float4 px4 = *(const float4*)(sv + c * VST);
            float4 wa = *(const float4*)(wk + c * FF);
            float4 wb = *(const float4*)(wk + c * FF + 4);
            float2 w2[4] = { make_float2(wa.x, wa.y), make_float2(wa.z, wa.w),
                             make_float2(wb.x, wb.y), make_float2(wb.z, wb.w) };
            float pv[4] = { px4.x, px4.y, px4.z, px4.w };
#pragma unroll
            for (int p = 0; p < 4; p++) {
                float2 pp = make_float2(pv[p], pv[p]);
#pragma unroll
                for (int j = 0; j < 4; j++) ffma2(acc[p][j], pp, w2[j]);
            }
        }
        __syncthreads();
    }

    // epilogue: bias + store (2 x STG.128 per pixel)
    float4 b0 = *(const float4*)(bias + fg * 8);
    float4 b1 = *(const float4*)(bias + fg * 8 + 4);
#pragma unroll
    for (int p = 0; p < 4; p++) {
        int row = pbase + pg * 4 + p;
        float* op = out + (size_t)row * FF + fg * 8;
        float4 o0 = make_float4(acc[p][0].x + b0.x, acc[p][0].y + b0.y,
                                acc[p][1].x + b0.z, acc[p][1].y + b0.w);
        float4 o1 = make_float4(acc[p][2].x + b1.x, acc[p][2].y + b1.y,
                                acc[p][3].x + b1.z, acc[p][3].y + b1.w);
        *(float4*)op = o0;
        *(float4*)(op + 4) = o1;
    }
}

// ---------------------------------------------------------------------------
extern "C" void kernel_launch(void* const* d_in, const int* in_sizes, int n_in,
                              void* d_out, int out_size)
{
    const float* x        = (const float*)d_in[0];
    const float* kern     = (const float*)d_in[1];
    const float* bias     = (const float*)d_in[2];
    const float* offset_w = (const float*)d_in[3];
    const float* offset_b = (const float*)d_in[4];
    float* out = (float*)d_out;

    noop_align<<<1, 32>>>();
    transpose_weights<<<(OWT_N + 255) / 256, 256>>>(offset_w);
    offsets_conv<<<(BB * HH * WW) / 8, 128>>>(x, offset_b);
    deform_main<<<(BB * HH * WW) / TILE, 128>>>(x, kern, bias, out);
}

// round 8
// speedup vs baseline: 6.4259x; 1.6055x over previous
#include <cuda_runtime.h>
#include <cuda_fp16.h>
#include <cstdint>

// Problem constants
#define BB 8
#define HH 64
#define WW 64
#define CC 128
#define FF 128
#define KKT 9
#define OO 18
#define MTILE 128           // pixels per CTA (= GEMM M)

// dynamic SMEM layout (byte offsets)
#define A_HI 0
#define A_LO 32768
#define POS_OFF 65536                    // int2[1152]
#define WT_OFF  (POS_OFF + 9216)         // float4[1152]
#define DYN_SMEM (WT_OFF + 18432)        // 93184 B

// scratch (no allocation allowed)
__device__ float g_offsets[BB * HH * WW * OO];     // [pix][18]
__device__ float g_owt[KKT * OO * CC];             // [k][o][c]
// B fragments, HMMA-register layout:
// [tap][kc][nh][i(4)][lane(32)] as uint4; each uint4 = regs for n-tiles 2i,2i+1
__device__ uint32_t g_bfrag[KKT * 8 * 2 * 4 * 32 * 4];

// ---------------------------------------------------------------------------
static __device__ __forceinline__ void ffma2(float2& d, float2 a, float2 b) {
    unsigned long long ud = *reinterpret_cast<unsigned long long*>(&d);
    unsigned long long ua = *reinterpret_cast<unsigned long long*>(&a);
    unsigned long long ub = *reinterpret_cast<unsigned long long*>(&b);
    asm("fma.rn.f32x2 %0, %1, %2, %0;" : "+l"(ud) : "l"(ua), "l"(ub));
    d = *reinterpret_cast<float2*>(&ud);
}

static __device__ __forceinline__ uint32_t smem_u32(const void* p) {
    uint32_t a;
    asm("{ .reg .u64 t; cvta.to.shared.u64 t, %1; cvt.u32.u64 %0, t; }"
        : "=r"(a) : "l"(p));
    return a;
}

#define LDM4(r0, r1, r2, r3, addr) \
    asm("ldmatrix.sync.aligned.m8n8.x4.shared.b16 {%0,%1,%2,%3}, [%4];" \
        : "=r"(r0), "=r"(r1), "=r"(r2), "=r"(r3) : "r"(addr))

#define MMA16816(c0, c1, c2, c3, a0, a1, a2, a3, b0, b1) \
    asm("mma.sync.aligned.m16n8k16.row.col.f32.f16.f16.f32 " \
        "{%0,%1,%2,%3}, {%4,%5,%6,%7}, {%8,%9}, {%0,%1,%2,%3};" \
        : "+f"(c0), "+f"(c1), "+f"(c2), "+f"(c3) \
        : "r"(a0), "r"(a1), "r"(a2), "r"(a3), "r"(b0), "r"(b1))

// launch-index alignment helper so ncu -s 5 lands on deform_main
__global__ void noop_align() {}

// ---------------------------------------------------------------------------
// Kernel 0: prep — offset-weight transpose + fp16 B-fragment packing.
// B fragment (m16n8k16, col-major B = [n][k] row-major weights^T):
//   reg b0 of lane l, n-tile nt: {W[k0+(l%4)*2][n], W[k0+(l%4)*2+1][n]}, n = nt*8+l/4
//   reg b1: same with k0+8.  k0 = kc*16.  W[k][n] = kern[tap][c=k][f=n].
// ---------------------------------------------------------------------------
#define OWT_N (KKT * OO * CC)
#define BFRAG_N (KKT * 8 * 2 * 4 * 32 * 4)
__global__ void prep_weights(const float* __restrict__ kern,
                             const float* __restrict__ ow) {
    int idx = blockIdx.x * 256 + threadIdx.x;
    if (idx < OWT_N) {
        int c = idx & (CC - 1);
        int rest = idx >> 7;
        int o = rest % OO;
        int k = rest / OO;
        g_owt[idx] = ow[(k * CC + c) * OO + o];
    }
    if (idx < BFRAG_N) {
        int j    = idx & 3;
        int lane = (idx >> 2) & 31;
        int i    = (idx >> 7) & 3;
        int nh   = (idx >> 9) & 1;
        int kc   = (idx >> 10) & 7;
        int tap  = idx >> 13;
        int nt    = i * 2 + (j >> 1);
        int which = j & 1;                       // b0 / b1
        int n = nh * 64 + nt * 8 + (lane >> 2);
        int k = kc * 16 + which * 8 + (lane & 3) * 2;
        float w0 = kern[((size_t)tap * CC + k) * FF + n];
        float w1 = kern[((size_t)tap * CC + k + 1) * FF + n];
        __half2 h2 = __floats2half2_rn(w0, w1);  // low = w0 (k), high = w1 (k+1)
        g_bfrag[idx] = *reinterpret_cast<uint32_t*>(&h2);
    }
}

// ---------------------------------------------------------------------------
// Kernel 1: offset-predicting 3x3 conv (unchanged — verified fp32 path)
// ---------------------------------------------------------------------------
__global__ __launch_bounds__(128) void offsets_conv(
    const float* __restrict__ x,
    const float* __restrict__ ob)
{
    int warp = threadIdx.x >> 5;
    int lane = threadIdx.x & 31;
    int pixA = blockIdx.x * 8 + warp * 2;
    int b = pixA >> 12;
    int rem = pixA & 4095;
    int y = rem >> 6;
    int xw = rem & 63;

    float2 accA[OO], accB[OO];
#pragma unroll
    for (int o = 0; o < OO; o++) { accA[o] = make_float2(0.f, 0.f); accB[o] = make_float2(0.f, 0.f); }

    const float* xb = x + (size_t)b * HH * WW * CC;

#pragma unroll
    for (int k = 0; k < KKT; k++) {
        int iy = y + k / 3 - 1;
        int ixA = xw + k % 3 - 1;
        float4 xA = make_float4(0.f, 0.f, 0.f, 0.f);
        float4 xB = make_float4(0.f, 0.f, 0.f, 0.f);
        if ((unsigned)iy < HH) {
            const float* rowp = xb + ((size_t)iy * WW) * CC + 4 * lane;
            if ((unsigned)ixA < WW) xA = *(const float4*)(rowp + ixA * CC);
            if ((unsigned)(ixA + 1) < WW) xB = *(const float4*)(rowp + (ixA + 1) * CC);
        }
        const float4* wv = (const float4*)(g_owt + k * OO * CC) + lane;
#pragma unroll
        for (int o = 0; o < OO; o++) {
            float4 w4 = wv[o * (CC / 4)];
            ffma2(accA[o], make_float2(xA.x, xA.y), make_float2(w4.x, w4.y));
            ffma2(accA[o], make_float2(xA.z, xA.w), make_float2(w4.z, w4.w));
            ffma2(accB[o], make_float2(xB.x, xB.y), make_float2(w4.x, w4.y));
            ffma2(accB[o], make_float2(xB.z, xB.w), make_float2(w4.z, w4.w));
        }
    }

#pragma unroll
    for (int o = 0; o < OO; o++) {
        float sA = accA[o].x + accA[o].y;
        float sB = accB[o].x + accB[o].y;
#pragma unroll
        for (int s = 16; s; s >>= 1) {
            sA += __shfl_down_sync(0xffffffffu, sA, s);
            sB += __shfl_down_sync(0xffffffffu, sB, s);
        }
        if (lane == 0) {
            float bo = ob[o];
            g_offsets[(size_t)pixA * OO + o] = sA + bo;
            g_offsets[(size_t)(pixA + 1) * OO + o] = sB + bo;
        }
    }
}

// ---------------------------------------------------------------------------
// Kernel 2: fused bilinear sampling + fp16-split HMMA GEMM + bias.
// CTA = 128 px x 128 f, 256 threads (8 warps: wm = wid&3 -> 32-px band,
// nh = wid>>2 -> 64-f half).  Per tap: Phase A sample->A_hi/A_lo smem tiles;
// Phase B: ldmatrix A frags + LDG.128 pre-packed B frags -> 2 HMMA products
// (a_hi*w + a_lo*w), f32 accum in registers.
// ---------------------------------------------------------------------------
__global__ __launch_bounds__(256) void deform_main(
    const float* __restrict__ x,
    const float* __restrict__ bias,
    float* __restrict__ out)
{
    extern __shared__ char ap[];
    uint32_t sbase = smem_u32(ap);

    int2*   spos = (int2*)(ap + POS_OFF);
    float4* swt  = (float4*)(ap + WT_OFF);

    const int tid = threadIdx.x;
    const int c = tid & 127;       // channel (phase A)
    const int thalf = tid >> 7;    // pixel half (phase A)
    const int wid = tid >> 5;
    const int lane = tid & 31;
    const int wm = wid & 3;        // M quarter (32 px)
    const int nh = wid >> 2;       // N half (64 f)

    int pbase = blockIdx.x * MTILE;
    int b = pbase >> 12;
    int rem = pbase & 4095;
    int ybase = rem >> 6;          // 128 px = 2 image rows

    // sampling positions for all (px, tap)
    for (int i = tid; i < MTILE * KKT; i += 256) {
        int t = i / KKT;
        int k = i - t * KKT;
        float dy = g_offsets[(size_t)(pbase + t) * OO + 2 * k];
        float dx = g_offsets[(size_t)(pbase + t) * OO + 2 * k + 1];
        float py = (float)(ybase + (t >> 6)) + (float)(k / 3 - 1) + dy;
        float px = (float)(t & 63) + (float)(k % 3 - 1) + dx;
        float fy = floorf(py), fx = floorf(px);
        spos[i] = make_int2((int)fy, (int)fx);
        float wy = py - fy, wx = px - fx;
        swt[i] = make_float4((1.f - wy) * (1.f - wx), (1.f - wy) * wx,
                             wy * (1.f - wx), wy * wx);
    }
    __syncthreads();

    float acc[2][8][4];
#pragma unroll
    for (int mt = 0; mt < 2; mt++)
#pragma unroll
        for (int nt = 0; nt < 8; nt++)
#pragma unroll
            for (int j = 0; j < 4; j++) acc[mt][nt][j] = 0.f;

    const float* xb = x + (size_t)b * HH * WW * CC;
    // ldmatrix per-thread address pieces (row within 16, col-half)
    const int lrow = lane & 15;
    const int lch = lane >> 4;     // 0: k0-7, 1: k8-15

    for (int k = 0; k < KKT; k++) {
        // ---- Phase A: sample + fp16 hi/lo split into A tiles ----
#pragma unroll 4
        for (int t = thalf * 64; t < thalf * 64 + 64; t++) {
            int i = t * KKT + k;
            int2 p = spos[i];
            float4 w = swt[i];
            int y0 = p.x, x0 = p.y;
            bool vy0 = (unsigned)y0 < HH;
            bool vy1 = (unsigned)(y0 + 1) < HH;
            bool vx0 = (unsigned)x0 < WW;
            bool vx1 = (unsigned)(x0 + 1) < WW;
            const float* basep = xb + ((y0 * WW + x0) * CC) + c;
            float v00 = (vy0 && vx0) ? basep[0] : 0.f;
            float v01 = (vy0 && vx1) ? basep[CC] : 0.f;
            float v10 = (vy1 && vx0) ? basep[WW * CC] : 0.f;
            float v11 = (vy1 && vx1) ? basep[WW * CC + CC] : 0.f;
            float val = w.x * v00 + w.y * v01 + w.z * v10 + w.w * v11;
            __half hi = __float2half_rn(val);
            __half lo = __float2half_rn(val - __half2float(hi));
            uint32_t off = (uint32_t)t * 256u
                         + ((((uint32_t)c >> 3) ^ ((uint32_t)t & 7)) << 4)
                         + ((uint32_t)c & 7) * 2u;
            *(__half*)(ap + A_HI + off) = hi;
            *(__half*)(ap + A_LO + off) = lo;
        }
        __syncthreads();

        // ---- Phase B: 8 k-chunks of 16 ----
#pragma unroll
        for (int kc = 0; kc < 8; kc++) {
            // A fragments (hi & lo) for both 16-row tiles of this warp's band
            uint32_t ah[2][4], al[2][4];
#pragma unroll
            for (int mt = 0; mt < 2; mt++) {
                int row = wm * 32 + mt * 16 + lrow;
                uint32_t chunk = (uint32_t)(kc * 2 + lch);
                uint32_t off = (uint32_t)row * 256u
                             + ((chunk ^ ((uint32_t)row & 7)) << 4);
                LDM4(ah[mt][0], ah[mt][1], ah[mt][2], ah[mt][3], sbase + A_HI + off);
                LDM4(al[mt][0], al[mt][1], al[mt][2], al[mt][3], sbase + A_LO + off);
            }
            // B fragments: 4 x LDG.128, pre-packed layout
            const uint4* bb = ((const uint4*)g_bfrag)
                            + ((((size_t)k * 8 + kc) * 2 + nh) * 4) * 32 + lane;
            uint4 bf0 = bb[0];
            uint4 bf1 = bb[32];
            uint4 bf2 = bb[64];
            uint4 bf3 = bb[96];
            uint32_t br[16] = { bf0.x, bf0.y, bf0.z, bf0.w,
                                bf1.x, bf1.y, bf1.z, bf1.w,
                                bf2.x, bf2.y, bf2.z, bf2.w,
                                bf3.x, bf3.y, bf3.z, bf3.w };
#pragma unroll
            for (int mt = 0; mt < 2; mt++)
#pragma unroll
                for (int nt = 0; nt < 8; nt++) {
                    MMA16816(acc[mt][nt][0], acc[mt][nt][1], acc[mt][nt][2], acc[mt][nt][3],
                             ah[mt][0], ah[mt][1], ah[mt][2], ah[mt][3],
                             br[nt * 2], br[nt * 2 + 1]);
                    MMA16816(acc[mt][nt][0], acc[mt][nt][1], acc[mt][nt][2], acc[mt][nt][3],
                             al[mt][0], al[mt][1], al[mt][2], al[mt][3],
                             br[nt * 2], br[nt * 2 + 1]);
                }
        }
        __syncthreads();
    }

    // ---- epilogue: bias + store ----
    // c0,c1 -> (row = band + lane/4, cols col0,col0+1); c2,c3 -> row+8
#pragma unroll
    for (int mt = 0; mt < 2; mt++) {
        int row0 = pbase + wm * 32 + mt * 16 + (lane >> 2);
#pragma unroll
        for (int nt = 0; nt < 8; nt++) {
            int col = nh * 64 + nt * 8 + (lane & 3) * 2;
            float2 bv = *(const float2*)(bias + col);
            *(float2*)(out + (size_t)row0 * FF + col) =
                make_float2(acc[mt][nt][0] + bv.x, acc[mt][nt][1] + bv.y);
            *(float2*)(out + (size_t)(row0 + 8) * FF + col) =
                make_float2(acc[mt][nt][2] + bv.x, acc[mt][nt][3] + bv.y);
        }
    }
}

// ---------------------------------------------------------------------------
extern "C" void kernel_launch(void* const* d_in, const int* in_sizes, int n_in,
                              void* d_out, int out_size)
{
    const float* x        = (const float*)d_in[0];
    const float* kern     = (const float*)d_in[1];
    const float* bias     = (const float*)d_in[2];
    const float* offset_w = (const float*)d_in[3];
    const float* offset_b = (const float*)d_in[4];
    float* out = (float*)d_out;

    cudaFuncSetAttribute(deform_main,
                         cudaFuncAttributeMaxDynamicSharedMemorySize, DYN_SMEM);

    noop_align<<<1, 32>>>();
    prep_weights<<<(BFRAG_N + 255) / 256, 256>>>(kern, offset_w);
    offsets_conv<<<(BB * HH * WW) / 8, 128>>>(x, offset_b);
    deform_main<<<(BB * HH * WW) / MTILE, 256, DYN_SMEM>>>(x, bias, out);
}

// round 9
// speedup vs baseline: 7.9250x; 1.2333x over previous
#include <cuda_runtime.h>
#include <cuda_fp16.h>
#include <cstdint>

// Problem constants
#define BB 8
#define HH 64
#define WW 64
#define CC 128
#define FF 128
#define KKT 9
#define OO 18
#define MTILE 128           // pixels per CTA (= GEMM M)

// dynamic SMEM layout (byte offsets)
#define A_B0 0
#define A_B1 32768
#define POS_OFF 65536                      // short4[1152] = 9216 B
#define WT_OFF  (POS_OFF + 9216)           // float4[1152] = 18432 B
#define DYN_SMEM (WT_OFF + 18432)          // 93184 B

// scratch (no allocation allowed)
__device__ float g_offsets[BB * HH * WW * OO];     // [pix][18]
__device__ float g_owt[KKT * OO * CC];             // [k][o][c]
// B fragments, HMMA-register layout, hi/lo split:
// [tap][kc][nh][i(4)][lane(32)] as uint4; each uint4 = regs for n-tiles 2i,2i+1
#define BFRAG_N (KKT * 8 * 2 * 4 * 32 * 4)
__device__ uint32_t g_bfhi[BFRAG_N];
__device__ uint32_t g_bflo[BFRAG_N];

// ---------------------------------------------------------------------------
static __device__ __forceinline__ void ffma2(float2& d, float2 a, float2 b) {
    unsigned long long ud = *reinterpret_cast<unsigned long long*>(&d);
    unsigned long long ua = *reinterpret_cast<unsigned long long*>(&a);
    unsigned long long ub = *reinterpret_cast<unsigned long long*>(&b);
    asm("fma.rn.f32x2 %0, %1, %2, %0;" : "+l"(ud) : "l"(ua), "l"(ub));
    d = *reinterpret_cast<float2*>(&ud);
}

static __device__ __forceinline__ uint32_t smem_u32(const void* p) {
    uint32_t a;
    asm("{ .reg .u64 t; cvta.to.shared.u64 t, %1; cvt.u32.u64 %0, t; }"
        : "=r"(a) : "l"(p));
    return a;
}

#define LDM4(r0, r1, r2, r3, addr) \
    asm("ldmatrix.sync.aligned.m8n8.x4.shared.b16 {%0,%1,%2,%3}, [%4];" \
        : "=r"(r0), "=r"(r1), "=r"(r2), "=r"(r3) : "r"(addr))

#define MMA16816(c0, c1, c2, c3, a0, a1, a2, a3, b0, b1) \
    asm("mma.sync.aligned.m16n8k16.row.col.f32.f16.f16.f32 " \
        "{%0,%1,%2,%3}, {%4,%5,%6,%7}, {%8,%9}, {%0,%1,%2,%3};" \
        : "+f"(c0), "+f"(c1), "+f"(c2), "+f"(c3) \
        : "r"(a0), "r"(a1), "r"(a2), "r"(a3), "r"(b0), "r"(b1))

// launch-index alignment helper so ncu -s 5 lands on deform_main
__global__ void noop_align() {}

// ---------------------------------------------------------------------------
// Kernel 0: prep — offset-weight transpose + fp16 hi/lo B-fragment packing.
// ---------------------------------------------------------------------------
#define OWT_N (KKT * OO * CC)
__global__ void prep_weights(const float* __restrict__ kern,
                             const float* __restrict__ ow) {
    int idx = blockIdx.x * 256 + threadIdx.x;
    if (idx < OWT_N) {
        int c = idx & (CC - 1);
        int rest = idx >> 7;
        int o = rest % OO;
        int k = rest / OO;
        g_owt[idx] = ow[(k * CC + c) * OO + o];
    }
    if (idx < BFRAG_N) {
        int j    = idx & 3;
        int lane = (idx >> 2) & 31;
        int i    = (idx >> 7) & 3;
        int nh   = (idx >> 9) & 1;
        int kc   = (idx >> 10) & 7;
        int tap  = idx >> 13;
        int nt    = i * 2 + (j >> 1);
        int which = j & 1;
        int n = nh * 64 + nt * 8 + (lane >> 2);
        int k = kc * 16 + which * 8 + (lane & 3) * 2;
        float w0 = kern[((size_t)tap * CC + k) * FF + n];
        float w1 = kern[((size_t)tap * CC + k + 1) * FF + n];
        __half h0 = __float2half_rn(w0);
        __half h1 = __float2half_rn(w1);
        __half l0 = __float2half_rn(w0 - __half2float(h0));
        __half l1 = __float2half_rn(w1 - __half2float(h1));
        __half2 hh = __halves2half2(h0, h1);
        __half2 ll = __halves2half2(l0, l1);
        g_bfhi[idx] = *reinterpret_cast<uint32_t*>(&hh);
        g_bflo[idx] = *reinterpret_cast<uint32_t*>(&ll);
    }
}

// ---------------------------------------------------------------------------
// Kernel 1: offset-predicting 3x3 conv (unchanged — verified fp32 path)
// ---------------------------------------------------------------------------
__global__ __launch_bounds__(128) void offsets_conv(
    const float* __restrict__ x,
    const float* __restrict__ ob)
{
    int warp = threadIdx.x >> 5;
    int lane = threadIdx.x & 31;
    int pixA = blockIdx.x * 8 + warp * 2;
    int b = pixA >> 12;
    int rem = pixA & 4095;
    int y = rem >> 6;
    int xw = rem & 63;

    float2 accA[OO], accB[OO];
#pragma unroll
    for (int o = 0; o < OO; o++) { accA[o] = make_float2(0.f, 0.f); accB[o] = make_float2(0.f, 0.f); }

    const float* xb = x + (size_t)b * HH * WW * CC;

#pragma unroll
    for (int k = 0; k < KKT; k++) {
        int iy = y + k / 3 - 1;
        int ixA = xw + k % 3 - 1;
        float4 xA = make_float4(0.f, 0.f, 0.f, 0.f);
        float4 xB = make_float4(0.f, 0.f, 0.f, 0.f);
        if ((unsigned)iy < HH) {
            const float* rowp = xb + ((size_t)iy * WW) * CC + 4 * lane;
            if ((unsigned)ixA < WW) xA = *(const float4*)(rowp + ixA * CC);
            if ((unsigned)(ixA + 1) < WW) xB = *(const float4*)(rowp + (ixA + 1) * CC);
        }
        const float4* wv = (const float4*)(g_owt + k * OO * CC) + lane;
#pragma unroll
        for (int o = 0; o < OO; o++) {
            float4 w4 = wv[o * (CC / 4)];
            ffma2(accA[o], make_float2(xA.x, xA.y), make_float2(w4.x, w4.y));
            ffma2(accA[o], make_float2(xA.z, xA.w), make_float2(w4.z, w4.w));
            ffma2(accB[o], make_float2(xB.x, xB.y), make_float2(w4.x, w4.y));
            ffma2(accB[o], make_float2(xB.z, xB.w), make_float2(w4.z, w4.w));
        }
    }

#pragma unroll
    for (int o = 0; o < OO; o++) {
        float sA = accA[o].x + accA[o].y;
        float sB = accB[o].x + accB[o].y;
#pragma unroll
        for (int s = 16; s; s >>= 1) {
            sA += __shfl_down_sync(0xffffffffu, sA, s);
            sB += __shfl_down_sync(0xffffffffu, sB, s);
        }
        if (lane == 0) {
            float bo = ob[o];
            g_offsets[(size_t)pixA * OO + o] = sA + bo;
            g_offsets[(size_t)(pixA + 1) * OO + o] = sB + bo;
        }
    }
}

// ---------------------------------------------------------------------------
// Kernel 2: fused bilinear sampling + fp16 HMMA GEMM (A fp16, B hi/lo split).
// CTA = 128 px x 128 f, 256 threads, double-buffered A tile, 1 sync/tap.
// Phase A: precomputed clamped coords + masked weights -> 4 unconditional
// LDGs per sample, 4-sample batches for MLP. Phase B: ldmatrix A + packed
// B frags -> A*Bhi + A*Blo HMMA, f32 accum.
// ---------------------------------------------------------------------------
__global__ __launch_bounds__(256, 2) void deform_main(
    const float* __restrict__ x,
    const float* __restrict__ bias,
    float* __restrict__ out)
{
    extern __shared__ char ap[];
    uint32_t sbase = smem_u32(ap);

    short4* sposs = (short4*)(ap + POS_OFF);
    float4* swt   = (float4*)(ap + WT_OFF);

    const int tid = threadIdx.x;
    const int c = tid & 127;       // channel (phase A)
    const int thalf = tid >> 7;    // pixel half (phase A)
    const int wid = tid >> 5;
    const int lane = tid & 31;
    const int wm = wid & 3;        // M quarter (32 px)
    const int nh = wid >> 2;       // N half (64 f)

    int pbase = blockIdx.x * MTILE;
    int b = pbase >> 12;
    int rem = pbase & 4095;
    int ybase = rem >> 6;          // 128 px = 2 image rows

    // setup: clamped corner coords + validity-masked bilinear weights
    for (int i = tid; i < MTILE * KKT; i += 256) {
        int t = i / KKT;
        int k = i - t * KKT;
        float dy = g_offsets[(size_t)(pbase + t) * OO + 2 * k];
        float dx = g_offsets[(size_t)(pbase + t) * OO + 2 * k + 1];
        float py = (float)(ybase + (t >> 6)) + (float)(k / 3 - 1) + dy;
        float px = (float)(t & 63) + (float)(k % 3 - 1) + dx;
        float fy = floorf(py), fx = floorf(px);
        int y0 = (int)fy, x0 = (int)fx;
        float wy = py - fy, wx = px - fx;
        bool vy0 = (unsigned)y0 < HH;
        bool vy1 = (unsigned)(y0 + 1) < HH;
        bool vx0 = (unsigned)x0 < WW;
        bool vx1 = (unsigned)(x0 + 1) < WW;
        float w00 = (vy0 && vx0) ? (1.f - wy) * (1.f - wx) : 0.f;
        float w01 = (vy0 && vx1) ? (1.f - wy) * wx : 0.f;
        float w10 = (vy1 && vx0) ? wy * (1.f - wx) : 0.f;
        float w11 = (vy1 && vx1) ? wy * wx : 0.f;
        int y0c = min(max(y0, 0), HH - 1);
        int y1c = min(max(y0 + 1, 0), HH - 1);
        int x0c = min(max(x0, 0), WW - 1);
        int x1c = min(max(x0 + 1, 0), WW - 1);
        sposs[i] = make_short4((short)y0c, (short)x0c, (short)y1c, (short)x1c);
        swt[i] = make_float4(w00, w01, w10, w11);
    }
    __syncthreads();

    float acc[2][8][4];
#pragma unroll
    for (int mt = 0; mt < 2; mt++)
#pragma unroll
        for (int nt = 0; nt < 8; nt++)
#pragma unroll
            for (int j = 0; j < 4; j++) acc[mt][nt][j] = 0.f;

    const float* xb = x + (size_t)b * HH * WW * CC;
    const int lrow = lane & 15;
    const int lch = lane >> 4;
    const int tbase = thalf * 64;

    for (int k = 0; k < KKT; k++) {
        const uint32_t abuf = (k & 1) ? A_B1 : A_B0;

        // ---- Phase A: batched unconditional gathers -> fp16 A tile ----
#pragma unroll 2
        for (int g = 0; g < 16; g++) {
            float val[4];
#pragma unroll
            for (int j = 0; j < 4; j++) {
                int t = tbase + g * 4 + j;
                int i = t * KKT + k;
                short4 p = sposs[i];
                float4 w = swt[i];
                const float* r0 = xb + ((int)p.x << 13) + c;
                const float* r1 = xb + ((int)p.z << 13) + c;
                float v00 = __ldg(r0 + ((int)p.y << 7));
                float v01 = __ldg(r0 + ((int)p.w << 7));
                float v10 = __ldg(r1 + ((int)p.y << 7));
                float v11 = __ldg(r1 + ((int)p.w << 7));
                val[j] = w.x * v00 + w.y * v01 + w.z * v10 + w.w * v11;
            }
#pragma unroll
            for (int j = 0; j < 4; j++) {
                int t = tbase + g * 4 + j;
                uint32_t off = (uint32_t)t * 256u
                             + ((((uint32_t)c >> 3) ^ ((uint32_t)t & 7)) << 4)
                             + ((uint32_t)c & 7) * 2u;
                *(__half*)(ap + abuf + off) = __float2half_rn(val[j]);
            }
        }
        __syncthreads();

        // ---- Phase B: 8 k-chunks of 16 ----
#pragma unroll
        for (int kc = 0; kc < 8; kc++) {
            uint32_t ah[2][4];
#pragma unroll
            for (int mt = 0; mt < 2; mt++) {
                int row = wm * 32 + mt * 16 + lrow;
                uint32_t chunk = (uint32_t)(kc * 2 + lch);
                uint32_t off = (uint32_t)row * 256u
                             + ((chunk ^ ((uint32_t)row & 7)) << 4);
                LDM4(ah[mt][0], ah[mt][1], ah[mt][2], ah[mt][3], sbase + abuf + off);
            }
            size_t bidx = ((((size_t)k * 8 + kc) * 2 + nh) * 4) * 32 + lane;

            // hi product
            {
                const uint4* bb = ((const uint4*)g_bfhi) + bidx;
                uint4 bf0 = bb[0], bf1 = bb[32], bf2 = bb[64], bf3 = bb[96];
                uint32_t br[16] = { bf0.x, bf0.y, bf0.z, bf0.w,
                                    bf1.x, bf1.y, bf1.z, bf1.w,
                                    bf2.x, bf2.y, bf2.z, bf2.w,
                                    bf3.x, bf3.y, bf3.z, bf3.w };
#pragma unroll
                for (int mt = 0; mt < 2; mt++)
#pragma unroll
                    for (int nt = 0; nt < 8; nt++)
                        MMA16816(acc[mt][nt][0], acc[mt][nt][1], acc[mt][nt][2], acc[mt][nt][3],
                                 ah[mt][0], ah[mt][1], ah[mt][2], ah[mt][3],
                                 br[nt * 2], br[nt * 2 + 1]);
            }
            // lo product
            {
                const uint4* bb = ((const uint4*)g_bflo) + bidx;
                uint4 bf0 = bb[0], bf1 = bb[32], bf2 = bb[64], bf3 = bb[96];
                uint32_t br[16] = { bf0.x, bf0.y, bf0.z, bf0.w,
                                    bf1.x, bf1.y, bf1.z, bf1.w,
                                    bf2.x, bf2.y, bf2.z, bf2.w,
                                    bf3.x, bf3.y, bf3.z, bf3.w };
#pragma unroll
                for (int mt = 0; mt < 2; mt++)
#pragma unroll
                    for (int nt = 0; nt < 8; nt++)
                        MMA16816(acc[mt][nt][0], acc[mt][nt][1], acc[mt][nt][2], acc[mt][nt][3],
                                 ah[mt][0], ah[mt][1], ah[mt][2], ah[mt][3],
                                 br[nt * 2], br[nt * 2 + 1]);
            }
        }
        // no trailing sync: next tap writes the other A buffer; the next
        // tap's post-Phase-A sync guarantees buffer reuse safety.
    }

    // ---- epilogue: bias + store ----
#pragma unroll
    for (int mt = 0; mt < 2; mt++) {
        int row0 = pbase + wm * 32 + mt * 16 + (lane >> 2);
#pragma unroll
        for (int nt = 0; nt < 8; nt++) {
            int col = nh * 64 + nt * 8 + (lane & 3) * 2;
            float2 bv = *(const float2*)(bias + col);
            *(float2*)(out + (size_t)row0 * FF + col) =
                make_float2(acc[mt][nt][0] + bv.x, acc[mt][nt][1] + bv.y);
            *(float2*)(out + (size_t)(row0 + 8) * FF + col) =
                make_float2(acc[mt][nt][2] + bv.x, acc[mt][nt][3] + bv.y);
        }
    }
}

// ---------------------------------------------------------------------------
extern "C" void kernel_launch(void* const* d_in, const int* in_sizes, int n_in,
                              void* d_out, int out_size)
{
    const float* x        = (const float*)d_in[0];
    const float* kern     = (const float*)d_in[1];
    const float* bias     = (const float*)d_in[2];
    const float* offset_w = (const float*)d_in[3];
    const float* offset_b = (const float*)d_in[4];
    float* out = (float*)d_out;

    cudaFuncSetAttribute(deform_main,
                         cudaFuncAttributeMaxDynamicSharedMemorySize, DYN_SMEM);

    noop_align<<<1, 32>>>();
    prep_weights<<<(BFRAG_N + 255) / 256, 256>>>(kern, offset_w);
    offsets_conv<<<(BB * HH * WW) / 8, 128>>>(x, offset_b);
    deform_main<<<(BB * HH * WW) / MTILE, 256, DYN_SMEM>>>(x, bias, out);
}

// round 11
// speedup vs baseline: 11.8908x; 1.5004x over previous
#include <cuda_runtime.h>
#include <cuda_fp16.h>
#include <cstdint>

// Problem constants
#define BB 8
#define HH 64
#define WW 64
#define CC 128
#define FF 128
#define KKT 9
#define OO 18
#define MTILE 128           // pixels per CTA (= GEMM M)

// deform_main dynamic SMEM layout (byte offsets)
#define A_B0 0
#define A_B1 32768
#define POS_OFF 65536                      // short4[1152] = 9216 B
#define WT_OFF  (POS_OFF + 9216)           // float4[1152] = 18432 B
#define DYN_SMEM (WT_OFF + 18432)          // 93184 B
// offsets_hmma dynamic SMEM: two 32 KB A buffers
#define OFF_SMEM 65536

// scratch (no allocation allowed)
__device__ float g_offsets[BB * HH * WW * OO];     // [pix][18]
// main-GEMM B fragments, HMMA-register layout, hi/lo split:
// [tap][kc][nh][i(4)][lane(32)] as uint4
#define BFRAG_N (KKT * 8 * 2 * 4 * 32 * 4)
__device__ uint32_t g_bfhi[BFRAG_N];
__device__ uint32_t g_bflo[BFRAG_N];
// offset-GEMM B fragments (N=32 padded from 18): [tap][kc][i(2)][lane] uint4
#define OBF_N (KKT * 8 * 2 * 32 * 4)
__device__ uint32_t g_obfhi[OBF_N];
__device__ uint32_t g_obflo[OBF_N];

// ---------------------------------------------------------------------------
static __device__ __forceinline__ void ffma2(float2& d, float2 a, float2 b) {
    unsigned long long ud = *reinterpret_cast<unsigned long long*>(&d);
    unsigned long long ua = *reinterpret_cast<unsigned long long*>(&a);
    unsigned long long ub = *reinterpret_cast<unsigned long long*>(&b);
    asm("fma.rn.f32x2 %0, %1, %2, %0;" : "+l"(ud) : "l"(ua), "l"(ub));
    d = *reinterpret_cast<float2*>(&ud);
}

static __device__ __forceinline__ uint32_t smem_u32(const void* p) {
    uint32_t a;
    asm("{ .reg .u64 t; cvta.to.shared.u64 t, %1; cvt.u32.u64 %0, t; }"
        : "=r"(a) : "l"(p));
    return a;
}

#define LDM4(r0, r1, r2, r3, addr) \
    asm("ldmatrix.sync.aligned.m8n8.x4.shared.b16 {%0,%1,%2,%3}, [%4];" \
        : "=r"(r0), "=r"(r1), "=r"(r2), "=r"(r3) : "r"(addr))

#define MMA16816(c0, c1, c2, c3, a0, a1, a2, a3, b0, b1) \
    asm("mma.sync.aligned.m16n8k16.row.col.f32.f16.f16.f32 " \
        "{%0,%1,%2,%3}, {%4,%5,%6,%7}, {%8,%9}, {%0,%1,%2,%3};" \
        : "+f"(c0), "+f"(c1), "+f"(c2), "+f"(c3) \
        : "r"(a0), "r"(a1), "r"(a2), "r"(a3), "r"(b0), "r"(b1))

// launch-index alignment helper so ncu -s 5 lands on deform_main
__global__ void noop_align() {}

// ---------------------------------------------------------------------------
// Kernel 0: prep — fp16 hi/lo B-fragment packing for both GEMMs.
// ---------------------------------------------------------------------------
__global__ void prep_weights(const float* __restrict__ kern,
                             const float* __restrict__ ow) {
    int idx = blockIdx.x * 256 + threadIdx.x;
    if (idx < BFRAG_N) {
        int j    = idx & 3;
        int lane = (idx >> 2) & 31;
        int i    = (idx >> 7) & 3;
        int nh   = (idx >> 9) & 1;
        int kc   = (idx >> 10) & 7;
        int tap  = idx >> 13;
        int nt    = i * 2 + (j >> 1);
        int which = j & 1;
        int n = nh * 64 + nt * 8 + (lane >> 2);
        int k = kc * 16 + which * 8 + (lane & 3) * 2;
        float w0 = kern[((size_t)tap * CC + k) * FF + n];
        float w1 = kern[((size_t)tap * CC + k + 1) * FF + n];
        __half h0 = __float2half_rn(w0);
        __half h1 = __float2half_rn(w1);
        __half l0 = __float2half_rn(w0 - __half2float(h0));
        __half l1 = __float2half_rn(w1 - __half2float(h1));
        __half2 hh = __halves2half2(h0, h1);
        __half2 ll = __halves2half2(l0, l1);
        g_bfhi[idx] = *reinterpret_cast<uint32_t*>(&hh);
        g_bflo[idx] = *reinterpret_cast<uint32_t*>(&ll);
    }
    if (idx < OBF_N) {
        int j    = idx & 3;
        int lane = (idx >> 2) & 31;
        int i    = (idx >> 7) & 1;
        int kc   = (idx >> 8) & 7;
        int tap  = idx >> 11;
        int nt    = i * 2 + (j >> 1);
        int which = j & 1;
        int n = nt * 8 + (lane >> 2);
        int k = kc * 16 + which * 8 + (lane & 3) * 2;
        float w0 = 0.f, w1 = 0.f;
        if (n < OO) {
            w0 = ow[((size_t)tap * CC + k) * OO + n];
            w1 = ow[((size_t)tap * CC + k + 1) * OO + n];
        }
        __half h0 = __float2half_rn(w0);
        __half h1 = __float2half_rn(w1);
        __half l0 = __float2half_rn(w0 - __half2float(h0));
        __half l1 = __float2half_rn(w1 - __half2float(h1));
        __half2 hh = __halves2half2(h0, h1);
        __half2 ll = __halves2half2(l0, l1);
        g_obfhi[idx] = *reinterpret_cast<uint32_t*>(&hh);
        g_obflo[idx] = *reinterpret_cast<uint32_t*>(&ll);
    }
}

// ---------------------------------------------------------------------------
// Kernel 1: offset-predicting 3x3 conv via HMMA.
// CTA = 128 px, 256 threads. Phase A: im2col tap shift (zero-pad) -> fp16
// A tile. Phase B: warp = one 16-px m-tile, N=32 (18 padded), B hi/lo.
// ---------------------------------------------------------------------------
__global__ __launch_bounds__(256) void offsets_hmma(
    const float* __restrict__ x,
    const float* __restrict__ ob)
{
    extern __shared__ char ap[];
    uint32_t sbase = smem_u32(ap);

    const int tid = threadIdx.x;
    const int cg = tid & 31;       // channel group (4 ch)
    const int pg = tid >> 5;       // pixel group (16 px)
    const int c0 = cg * 4;
    const int wid = tid >> 5;
    const int lane = tid & 31;
    const int lrow = lane & 15;
    const int lch = lane >> 4;

    int pbase = blockIdx.x * MTILE;
    int b = pbase >> 12;
    int ybase = (pbase & 4095) >> 6;

    const float* xb = x + (size_t)b * HH * WW * CC;

    float acc[4][4];
#pragma unroll
    for (int nt = 0; nt < 4; nt++)
#pragma unroll
        for (int j = 0; j < 4; j++) acc[nt][j] = 0.f;

    for (int k = 0; k < KKT; k++) {
        const uint32_t abuf = (k & 1) ? (uint32_t)A_B1 : (uint32_t)A_B0;
        int dyk = k / 3 - 1, dxk = k % 3 - 1;

        // ---- Phase A: shifted copy with zero pad ----
#pragma unroll 4
        for (int j = 0; j < 16; j++) {
            int t = pg * 16 + j;
            int iy = ybase + (t >> 6) + dyk;
            int ix = (t & 63) + dxk;
            float4 v = make_float4(0.f, 0.f, 0.f, 0.f);
            if ((unsigned)iy < HH && (unsigned)ix < WW)
                v = *(const float4*)(xb + ((iy << 6) + ix) * CC + c0);
            __half2 h01 = __floats2half2_rn(v.x, v.y);
            __half2 h23 = __floats2half2_rn(v.z, v.w);
            uint32_t off = (uint32_t)t * 256u
                         + ((((uint32_t)c0 >> 3) ^ ((uint32_t)t & 7)) << 4)
                         + ((uint32_t)c0 & 7) * 2u;
            uint2 pk;
            pk.x = *reinterpret_cast<uint32_t*>(&h01);
            pk.y = *reinterpret_cast<uint32_t*>(&h23);
            *(uint2*)(ap + abuf + off) = pk;
        }
        __syncthreads();

        // ---- Phase B: warp = 16-px m-tile, N=32 ----
#pragma unroll
        for (int kc = 0; kc < 8; kc++) {
            int row = wid * 16 + lrow;
            uint32_t chunk = (uint32_t)(kc * 2 + lch);
            uint32_t aoff = (uint32_t)row * 256u
                          + ((chunk ^ ((uint32_t)row & 7)) << 4);
            uint32_t a0, a1, a2, a3;
            LDM4(a0, a1, a2, a3, sbase + abuf + aoff);

            size_t bidx = (((size_t)k * 8 + kc) * 2) * 32 + lane;
            const uint4* bh = ((const uint4*)g_obfhi) + bidx;
            const uint4* bl = ((const uint4*)g_obflo) + bidx;
            uint4 bh0 = bh[0], bh1 = bh[32];
            uint4 bl0 = bl[0], bl1 = bl[32];
            uint32_t brh[8] = { bh0.x, bh0.y, bh0.z, bh0.w, bh1.x, bh1.y, bh1.z, bh1.w };
            uint32_t brl[8] = { bl0.x, bl0.y, bl0.z, bl0.w, bl1.x, bl1.y, bl1.z, bl1.w };
#pragma unroll
            for (int nt = 0; nt < 4; nt++) {
                MMA16816(acc[nt][0], acc[nt][1], acc[nt][2], acc[nt][3],
                         a0, a1, a2, a3, brh[nt * 2], brh[nt * 2 + 1]);
                MMA16816(acc[nt][0], acc[nt][1], acc[nt][2], acc[nt][3],
                         a0, a1, a2, a3, brl[nt * 2], brl[nt * 2 + 1]);
            }
        }
    }

    // ---- epilogue: + offset bias, store to g_offsets ----
    {
        int r0 = pbase + wid * 16 + (lane >> 2);
#pragma unroll
        for (int nt = 0; nt < 3; nt++) {          // nt=3 -> cols 24..31, all pad
            int col = nt * 8 + (lane & 3) * 2;
            if (col < OO) {
                float2 ob2 = *(const float2*)(ob + col);
                *(float2*)(g_offsets + (size_t)r0 * OO + col) =
                    make_float2(acc[nt][0] + ob2.x, acc[nt][1] + ob2.y);
                *(float2*)(g_offsets + (size_t)(r0 + 8) * OO + col) =
                    make_float2(acc[nt][2] + ob2.x, acc[nt][3] + ob2.y);
            }
        }
    }
}

// ---------------------------------------------------------------------------
// Kernel 2: fused bilinear sampling + fp16 HMMA GEMM (A fp16, B hi/lo split).
// Phase A vectorized: thread = 4 channels x 16 pixels, LDG.128 + STS.64.
// ---------------------------------------------------------------------------
__global__ __launch_bounds__(256, 2) void deform_main(
    const float* __restrict__ x,
    const float* __restrict__ bias,
    float* __restrict__ out)
{
    extern __shared__ char ap[];
    uint32_t sbase = smem_u32(ap);

    short4* sposs = (short4*)(ap + POS_OFF);
    float4* swt   = (float4*)(ap + WT_OFF);

    const int tid = threadIdx.x;
    const int cg = tid & 31;       // channel group (4 ch)
    const int pg = tid >> 5;       // pixel group (16 px)
    const int c0 = cg * 4;
    const int wid = tid >> 5;
    const int lane = tid & 31;
    const int wm = wid & 3;        // M quarter (32 px)
    const int nh = wid >> 2;       // N half (64 f)

    int pbase = blockIdx.x * MTILE;
    int b = pbase >> 12;
    int rem = pbase & 4095;
    int ybase = rem >> 6;

    // setup: clamped corner coords + validity-masked bilinear weights
    for (int i = tid; i < MTILE * KKT; i += 256) {
        int t = i / KKT;
        int k = i - t * KKT;
        float dy = g_offsets[(size_t)(pbase + t) * OO + 2 * k];
        float dx = g_offsets[(size_t)(pbase + t) * OO + 2 * k + 1];
        float py = (float)(ybase + (t >> 6)) + (float)(k / 3 - 1) + dy;
        float px = (float)(t & 63) + (float)(k % 3 - 1) + dx;
        float fy = floorf(py), fx = floorf(px);
        int y0 = (int)fy, x0 = (int)fx;
        float wy = py - fy, wx = px - fx;
        bool vy0 = (unsigned)y0 < HH;
        bool vy1 = (unsigned)(y0 + 1) < HH;
        bool vx0 = (unsigned)x0 < WW;
        bool vx1 = (unsigned)(x0 + 1) < WW;
        float w00 = (vy0 && vx0) ? (1.f - wy) * (1.f - wx) : 0.f;
        float w01 = (vy0 && vx1) ? (1.f - wy) * wx : 0.f;
        float w10 = (vy1 && vx0) ? wy * (1.f - wx) : 0.f;
        float w11 = (vy1 && vx1) ? wy * wx : 0.f;
        int y0c = min(max(y0, 0), HH - 1);
        int y1c = min(max(y0 + 1, 0), HH - 1);
        int x0c = min(max(x0, 0), WW - 1);
        int x1c = min(max(x0 + 1, 0), WW - 1);
        sposs[i] = make_short4((short)y0c, (short)x0c, (short)y1c, (short)x1c);
        swt[i] = make_float4(w00, w01, w10, w11);
    }
    __syncthreads();

    float acc[2][8][4];
#pragma unroll
    for (int mt = 0; mt < 2; mt++)
#pragma unroll
        for (int nt = 0; nt < 8; nt++)
#pragma unroll
            for (int j = 0; j < 4; j++) acc[mt][nt][j] = 0.f;

    const float* xb = x + (size_t)b * HH * WW * CC;
    const int lrow = lane & 15;
    const int lch = lane >> 4;

    for (int k = 0; k < KKT; k++) {
        const uint32_t abuf = (k & 1) ? (uint32_t)A_B1 : (uint32_t)A_B0;

        // ---- Phase A: vectorized gathers (4 ch x 16 px per thread) ----
#pragma unroll 4
        for (int j = 0; j < 16; j++) {
            int t = pg * 16 + j;
            int i = t * KKT + k;
            short4 p = sposs[i];      // warp-broadcast
            float4 w = swt[i];        // warp-broadcast
            const float* r0 = xb + ((int)p.x << 13) + c0;
            const float* r1 = xb + ((int)p.z << 13) + c0;
            float4 v00 = *(const float4*)(r0 + ((int)p.y << 7));
            float4 v01 = *(const float4*)(r0 + ((int)p.w << 7));
            float4 v10 = *(const float4*)(r1 + ((int)p.y << 7));
            float4 v11 = *(const float4*)(r1 + ((int)p.w << 7));
            float2 s01 = make_float2(0.f, 0.f), s23 = make_float2(0.f, 0.f);
            ffma2(s01, make_float2(v00.x, v00.y), make_float2(w.x, w.x));
            ffma2(s23, make_float2(v00.z, v00.w), make_float2(w.x, w.x));
            ffma2(s01, make_float2(v01.x, v01.y), make_float2(w.y, w.y));
            ffma2(s23, make_float2(v01.z, v01.w), make_float2(w.y, w.y));
            ffma2(s01, make_float2(v10.x, v10.y), make_float2(w.z, w.z));
            ffma2(s23, make_float2(v10.z, v10.w), make_float2(w.z, w.z));
            ffma2(s01, make_float2(v11.x, v11.y), make_float2(w.w, w.w));
            ffma2(s23, make_float2(v11.z, v11.w), make_float2(w.w, w.w));
            __half2 h01 = __floats2half2_rn(s01.x, s01.y);
            __half2 h23 = __floats2half2_rn(s23.x, s23.y);
            uint32_t off = (uint32_t)t * 256u
                         + ((((uint32_t)c0 >> 3) ^ ((uint32_t)t & 7)) << 4)
                         + ((uint32_t)c0 & 7) * 2u;
            uint2 pk;
            pk.x = *reinterpret_cast<uint32_t*>(&h01);
            pk.y = *reinterpret_cast<uint32_t*>(&h23);
            *(uint2*)(ap + abuf + off) = pk;
        }
        __syncthreads();

        // ---- Phase B: 8 k-chunks of 16 ----
#pragma unroll
        for (int kc = 0; kc < 8; kc++) {
            uint32_t ah[2][4];
#pragma unroll
            for (int mt = 0; mt < 2; mt++) {
                int row = wm * 32 + mt * 16 + lrow;
                uint32_t chunk = (uint32_t)(kc * 2 + lch);
                uint32_t off = (uint32_t)row * 256u
                             + ((chunk ^ ((uint32_t)row & 7)) << 4);
                LDM4(ah[mt][0], ah[mt][1], ah[mt][2], ah[mt][3], sbase + abuf + off);
            }
            size_t bidx = ((((size_t)k * 8 + kc) * 2 + nh) * 4) * 32 + lane;

            {
                const uint4* bb = ((const uint4*)g_bfhi) + bidx;
                uint4 bf0 = bb[0], bf1 = bb[32], bf2 = bb[64], bf3 = bb[96];
                uint32_t br[16] = { bf0.x, bf0.y, bf0.z, bf0.w,
                                    bf1.x, bf1.y, bf1.z, bf1.w,
                                    bf2.x, bf2.y, bf2.z, bf2.w,
                                    bf3.x, bf3.y, bf3.z, bf3.w };
#pragma unroll
                for (int mt = 0; mt < 2; mt++)
#pragma unroll
                    for (int nt = 0; nt < 8; nt++)
                        MMA16816(acc[mt][nt][0], acc[mt][nt][1], acc[mt][nt][2], acc[mt][nt][3],
                                 ah[mt][0], ah[mt][1], ah[mt][2], ah[mt][3],
                                 br[nt * 2], br[nt * 2 + 1]);
            }
            {
                const uint4* bb = ((const uint4*)g_bflo) + bidx;
                uint4 bf0 = bb[0], bf1 = bb[32], bf2 = bb[64], bf3 = bb[96];
                uint32_t br[16] = { bf0.x, bf0.y, bf0.z, bf0.w,
                                    bf1.x, bf1.y, bf1.z, bf1.w,
                                    bf2.x, bf2.y, bf2.z, bf2.w,
                                    bf3.x, bf3.y, bf3.z, bf3.w };
#pragma unroll
                for (int mt = 0; mt < 2; mt++)
#pragma unroll
                    for (int nt = 0; nt < 8; nt++)
                        MMA16816(acc[mt][nt][0], acc[mt][nt][1], acc[mt][nt][2], acc[mt][nt][3],
                                 ah[mt][0], ah[mt][1], ah[mt][2], ah[mt][3],
                                 br[nt * 2], br[nt * 2 + 1]);
            }
        }
        // no trailing sync: double-buffered A; next tap's post-Phase-A sync
        // guarantees all warps left the buffer being overwritten.
    }

    // ---- epilogue: bias + store ----
#pragma unroll
    for (int mt = 0; mt < 2; mt++) {
        int row0 = pbase + wm * 32 + mt * 16 + (lane >> 2);
#pragma unroll
        for (int nt = 0; nt < 8; nt++) {
            int col = nh * 64 + nt * 8 + (lane & 3) * 2;
            float2 bv = *(const float2*)(bias + col);
            *(float2*)(out + (size_t)row0 * FF + col) =
                make_float2(acc[mt][nt][0] + bv.x, acc[mt][nt][1] + bv.y);
            *(float2*)(out + (size_t)(row0 + 8) * FF + col) =
                make_float2(acc[mt][nt][2] + bv.x, acc[mt][nt][3] + bv.y);
        }
    }
}

// ---------------------------------------------------------------------------
extern "C" void kernel_launch(void* const* d_in, const int* in_sizes, int n_in,
                              void* d_out, int out_size)
{
    const float* x        = (const float*)d_in[0];
    const float* kern     = (const float*)d_in[1];
    const float* bias     = (const float*)d_in[2];
    const float* offset_w = (const float*)d_in[3];
    const float* offset_b = (const float*)d_in[4];
    float* out = (float*)d_out;

    cudaFuncSetAttribute(deform_main,
                         cudaFuncAttributeMaxDynamicSharedMemorySize, DYN_SMEM);
    cudaFuncSetAttribute(offsets_hmma,
                         cudaFuncAttributeMaxDynamicSharedMemorySize, OFF_SMEM);

    noop_align<<<1, 32>>>();
    prep_weights<<<(BFRAG_N + 255) / 256, 256>>>(kern, offset_w);
    offsets_hmma<<<(BB * HH * WW) / MTILE, 256, OFF_SMEM>>>(x, offset_b);
    deform_main<<<(BB * HH * WW) / MTILE, 256, DYN_SMEM>>>(x, bias, out);
}